// round 13
// baseline (speedup 1.0000x reference)
#include <cuda_runtime.h>
#include <math.h>
#include <stdint.h>

// Problem dims: B=8, T=1024, E=1024, H=16, HD=64, FF=4096, M = B*T = 8192

// ---------------- scratch (device globals; no allocations allowed) ----------
__device__ float g_qkv[(size_t)8192 * 3072];
__device__ float g_attn[(size_t)8192 * 1024];
__device__ float g_s[(size_t)8192 * 1024];
__device__ float g_x1[(size_t)8192 * 1024];
__device__ float g_ff[(size_t)8192 * 4096];
__device__ float g_wq[12582912];   // rounded weights: in_w 0, out_w 3145728, fc1_w 4194304, fc2_w 8388608
__device__ int   g_len[8];

// ---------------- padding-mask: dtype detect + parallel length extraction ---
__global__ void mask_len_kernel(const void* mask) {
    __shared__ int flags[3];           // 0: f32, 1: gt1 (u8), 2: eq1 (i32)
    __shared__ int lensh[8];
    const int tid = threadIdx.x;
    if (tid < 3) flags[tid] = 0;
    if (tid < 8) lensh[tid] = 1024;
    __syncthreads();

    const unsigned int* w = (const unsigned int*)mask;
    int f32 = 0, gt1 = 0, eq1 = 0;
    for (int i = tid; i < 2048; i += 256) {
        unsigned int v = w[i];
        if (v == 0x3F800000u)      f32 = 1;
        else if (v == 1u)          eq1 = 1;
        else if (v != 0u)          gt1 = 1;
    }
    if (f32) atomicOr(&flags[0], 1);
    if (gt1) atomicOr(&flags[1], 1);
    if (eq1) atomicOr(&flags[2], 1);
    __syncthreads();

    if (flags[0]) {
        const float* p = (const float*)mask;
        for (int i = tid; i < 8192; i += 256)
            if (p[i] != 0.f) atomicMin(&lensh[i >> 10], i & 1023);
    } else if (flags[1]) {
        const unsigned char* p = (const unsigned char*)mask;
        for (int i = tid; i < 8192; i += 256)
            if (p[i]) atomicMin(&lensh[i >> 10], i & 1023);
    } else if (flags[2]) {
        const int* p = (const int*)mask;
        for (int i = tid; i < 8192; i += 256)
            if (p[i]) atomicMin(&lensh[i >> 10], i & 1023);
    }
    __syncthreads();
    if (tid < 8) g_len[tid] = lensh[tid];
}

// ---------------- common helpers -------------------------------------------
__device__ __forceinline__ uint32_t f2tf(float x) {
    uint32_t r;
    asm("cvt.rna.tf32.f32 %0, %1;" : "=r"(r) : "f"(x));
    return r;
}
__device__ __forceinline__ void mma_tf32(float* d, const uint32_t* a, const uint32_t* b) {
    asm volatile(
        "mma.sync.aligned.m16n8k8.row.col.f32.tf32.tf32.f32 "
        "{%0,%1,%2,%3}, {%4,%5,%6,%7}, {%8,%9}, {%0,%1,%2,%3};"
        : "+f"(d[0]), "+f"(d[1]), "+f"(d[2]), "+f"(d[3])
        : "r"(a[0]), "r"(a[1]), "r"(a[2]), "r"(a[3]), "r"(b[0]), "r"(b[1]));
}
__device__ __forceinline__ void ldsm4(uint32_t& r0, uint32_t& r1, uint32_t& r2, uint32_t& r3,
                                      uint32_t addr) {
    asm volatile("ldmatrix.sync.aligned.m8n8.x4.shared.b16 {%0,%1,%2,%3}, [%4];"
                 : "=r"(r0), "=r"(r1), "=r"(r2), "=r"(r3) : "r"(addr));
}
__device__ __forceinline__ uint32_t s2u(const void* p) {
    return (uint32_t)__cvta_generic_to_shared(p);
}
__device__ __forceinline__ void cpasync16(uint32_t dst, const void* src) {
    asm volatile("cp.async.cg.shared.global [%0], [%1], 16;"
                 :: "r"(dst), "l"(src) : "memory");
}

// ---------------- merged tf32 RNA weight-rounding pass ----------------------
__global__ __launch_bounds__(256) void cvt_all_kernel(
    const float* __restrict__ in_w, const float* __restrict__ out_w,
    const float* __restrict__ fc1_w, const float* __restrict__ fc2_w,
    float* __restrict__ wq)
{
    int i = blockIdx.x * 256 + threadIdx.x;     // float4 index, < 3145728
    const float4* src;
    float4* dst;
    if (i < 786432) {
        src = (const float4*)in_w + i;           dst = (float4*)wq + i;
    } else if (i < 1048576) {
        int j = i - 786432;
        src = (const float4*)out_w + j;          dst = (float4*)(wq + 3145728) + j;
    } else if (i < 2097152) {
        int j = i - 1048576;
        src = (const float4*)fc1_w + j;          dst = (float4*)(wq + 4194304) + j;
    } else {
        int j = i - 2097152;
        src = (const float4*)fc2_w + j;          dst = (float4*)(wq + 8388608) + j;
    }
    float4 v = *src;
    float4 o;
    o.x = __uint_as_float(f2tf(v.x));
    o.y = __uint_as_float(f2tf(v.y));
    o.z = __uint_as_float(f2tf(v.z));
    o.w = __uint_as_float(f2tf(v.w));
    *dst = o;
}

// ---------------- tf32 tensor-core GEMM (R7 config, proven fastest) ---------
template <int EPI, bool ROUND_OUT>  // EPI 0: +bias, 1: +bias+res, 2: +bias+relu
__global__ __launch_bounds__(256, 2) void tgemm_kernel(
    const float* __restrict__ A, const float* __restrict__ W,
    const float* __restrict__ bias, const float* __restrict__ R,
    float* __restrict__ C, int Ksz, int Nsz)
{
    extern __shared__ uint32_t smem[];   // 4 stages x 16KB = 64KB
    const uint32_t sbase = s2u(smem);

    const int tid  = threadIdx.x;
    const int lane = tid & 31;
    const int warp = tid >> 5;
    const int wm   = warp & 3;
    const int wn   = warp >> 2;
    const int m0   = blockIdx.y * 128;
    const int n0   = blockIdx.x * 128;

    const int sr = tid >> 2;             // 0..63
    const int sc = tid & 3;
    const uint32_t swz = 4 * (sc ^ ((sr >> 1) & 3));
    const uint32_t dA0 = (sr * 16 + swz) * 4;
    const uint32_t dA1 = ((sr + 64) * 16 + swz) * 4;

    const float* Ap0 = A + (size_t)(m0 + sr) * Ksz + sc * 4;
    const float* Ap1 = A + (size_t)(m0 + sr + 64) * Ksz + sc * 4;
    const float* Wp0 = W + (size_t)(n0 + sr) * Ksz + sc * 4;
    const float* Wp1 = W + (size_t)(n0 + sr + 64) * Ksz + sc * 4;

    const int mat = lane >> 3, rr = lane & 7;
    const int ar  = wm * 32 + (mat & 1) * 8 + rr;
    const int ac  = mat >> 1;
    const uint32_t aA = sbase + (ar * 16 + 4 * (ac ^ ((ar >> 1) & 3))) * 4;
    const int br  = wn * 64 + (mat >> 1) * 8 + rr;
    const int bc  = mat & 1;
    const uint32_t aB = sbase + 8192 + (br * 16 + 4 * (bc ^ ((br >> 1) & 3))) * 4;

    float acc[2][8][4];
#pragma unroll
    for (int i = 0; i < 2; ++i)
#pragma unroll
        for (int j = 0; j < 8; ++j)
#pragma unroll
            for (int r = 0; r < 4; ++r) acc[i][j][r] = 0.f;

    const int KT = Ksz >> 4;

#pragma unroll
    for (int p = 0; p < 3; ++p) {
        const uint32_t st = sbase + p * 16384;
        cpasync16(st + dA0,        Ap0 + p * 16);
        cpasync16(st + dA1,        Ap1 + p * 16);
        cpasync16(st + 8192 + dA0, Wp0 + p * 16);
        cpasync16(st + 8192 + dA1, Wp1 + p * 16);
        asm volatile("cp.async.commit_group;" ::: "memory");
    }

    for (int kt = 0; kt < KT; ++kt) {
        asm volatile("cp.async.wait_group 2;" ::: "memory");
        __syncthreads();

        if (kt + 3 < KT) {
            const uint32_t st = sbase + ((kt + 3) & 3) * 16384;
            cpasync16(st + dA0,        Ap0 + (kt + 3) * 16);
            cpasync16(st + dA1,        Ap1 + (kt + 3) * 16);
            cpasync16(st + 8192 + dA0, Wp0 + (kt + 3) * 16);
            cpasync16(st + 8192 + dA1, Wp1 + (kt + 3) * 16);
        }
        asm volatile("cp.async.commit_group;" ::: "memory");

        const uint32_t off = (kt & 3) * 16384;
        const uint32_t aAb = aA + off;
        const uint32_t aBb = aB + off;
#pragma unroll
        for (int kk8 = 0; kk8 < 2; ++kk8) {
            const uint32_t xo = kk8 << 5;
            uint32_t af0[4], af1[4];
            ldsm4(af0[0], af0[1], af0[2], af0[3], aAb ^ xo);
            ldsm4(af1[0], af1[1], af1[2], af1[3], (aAb + 1024) ^ xo);
#pragma unroll
            for (int jp = 0; jp < 4; ++jp) {
                uint32_t bf[4];
                ldsm4(bf[0], bf[1], bf[2], bf[3], (aBb + jp * 1024) ^ xo);
                mma_tf32(acc[0][2 * jp],     af0, &bf[0]);
                mma_tf32(acc[1][2 * jp],     af1, &bf[0]);
                mma_tf32(acc[0][2 * jp + 1], af0, &bf[2]);
                mma_tf32(acc[1][2 * jp + 1], af1, &bf[2]);
            }
        }
    }

#pragma unroll
    for (int i = 0; i < 2; ++i) {
        int row = m0 + wm * 32 + i * 16 + (lane >> 2);
#pragma unroll
        for (int j = 0; j < 8; ++j) {
            int col = n0 + wn * 64 + j * 8 + (lane & 3) * 2;
            float b0v = bias[col], b1v = bias[col + 1];
            size_t o0 = (size_t)row * Nsz + col;
            size_t o1 = (size_t)(row + 8) * Nsz + col;
            float v0 = acc[i][j][0] + b0v, v1 = acc[i][j][1] + b1v;
            float v2 = acc[i][j][2] + b0v, v3 = acc[i][j][3] + b1v;
            if (EPI == 1) {
                v0 += R[o0]; v1 += R[o0 + 1];
                v2 += R[o1]; v3 += R[o1 + 1];
            }
            if (EPI == 2) {
                v0 = fmaxf(v0, 0.f); v1 = fmaxf(v1, 0.f);
                v2 = fmaxf(v2, 0.f); v3 = fmaxf(v3, 0.f);
            }
            if (ROUND_OUT) {
                v0 = __uint_as_float(f2tf(v0)); v1 = __uint_as_float(f2tf(v1));
                v2 = __uint_as_float(f2tf(v2)); v3 = __uint_as_float(f2tf(v3));
            }
            float2 q0v = { v0, v1 }, q1v = { v2, v3 };
            *(float2*)&C[o0] = q0v;
            *(float2*)&C[o1] = q1v;
        }
    }
}

// ---------------- attention: 128-query tile, 8 warps, private P region ------
// Q tile 128x64 (32KB), K 64x64 (16KB), Vt 64x64 (16KB), P 128x64 (32KB).
// K/V staging + V transpose amortized over 2x the queries vs the 64-row
// version; P in its own region -> PV A-frags read only the warp's own rows,
// so the all-block barriers around the P store become a __syncwarp().
__device__ __forceinline__ uint32_t aswz(uint32_t base, int row, int chunk) {
    int pos = (chunk & 8) | ((chunk & 7) ^ (row & 7));
    return base + (row * 64 + 4 * pos) * 4;
}

static constexpr int ATTN_SMEM = 98304;   // 96KB dynamic

__global__ __launch_bounds__(256, 2) void attn_kernel(
    const float* __restrict__ qkv, const int* __restrict__ lenv,
    float* __restrict__ out)
{
    extern __shared__ uint32_t asm_buf[];
    const uint32_t Qb = s2u(asm_buf);            // 128x64 words
    const uint32_t Kb = Qb + 32768;              // 64x64
    const uint32_t Vb = Kb + 16384;              // 64x64 (transposed)
    const uint32_t Pb = Vb + 16384;              // 128x64
    uint32_t* Qs = asm_buf;
    uint32_t* Ks = asm_buf + 8192;
    uint32_t* Vt = asm_buf + 12288;
    uint32_t* Ps = asm_buf + 16384;

    const int tid  = threadIdx.x;
    const int lane = tid & 31;
    const int wrp  = tid >> 5;        // 0..7, queries [wrp*16, wrp*16+16)
    const int b    = blockIdx.z;
    const int h    = blockIdx.y;
    const int qt   = blockIdx.x;      // 128-query tiles
    const int q0   = qt * 128;
    const int blen = lenv[b];
    const float scale = 0.125f;

    // load Q tile 128x64 (pre-scaled, raw fp32 bits)
    for (int i = tid; i < 128 * 16; i += 256) {
        int r = i >> 4, c4 = i & 15;
        float4 v = *(const float4*)&qkv[(size_t)(b * 1024 + q0 + r) * 3072 + h * 64 + c4 * 4];
        int pos = (c4 & 8) | ((c4 & 7) ^ (r & 7));
        uint32_t t[4] = { __float_as_uint(v.x * scale), __float_as_uint(v.y * scale),
                          __float_as_uint(v.z * scale), __float_as_uint(v.w * scale) };
        *(uint4*)&Qs[r * 64 + 4 * pos] = *(uint4*)t;
    }

    const int mat = lane >> 3, rr = lane & 7;
    const int g   = lane >> 2;
    const int q2  = lane & 3;
    const int aRowQ = wrp * 16 + (mat & 1) * 8 + rr;   // rows in Q/P (0..127)
    const int cbitA = mat >> 1;
    const int cbitB = mat & 1;
    const int bRowOff = (mat >> 1) * 8 + rr;           // rows in K/Vt 16-row pairs

    float O[8][4];
    float m0r = -1e30f, m1r = -1e30f, l0r = 0.f, l1r = 0.f;
#pragma unroll
    for (int j = 0; j < 8; ++j)
#pragma unroll
        for (int r = 0; r < 4; ++r) O[j][r] = 0.f;

    const int ktmax = 2 * qt + 1;     // key tiles of 64 covering q0..q0+127
    for (int kt = 0; kt <= ktmax && kt * 64 < blen; ++kt) {
        const int k0 = kt * 64;
        __syncthreads();   // prior-iter PV reads of Vt (and P) done; Q ready (kt=0)

        // K tile -> Ks [key][d]
        for (int i = tid; i < 64 * 16; i += 256) {
            int r = i >> 4, c4 = i & 15;
            float4 v = *(const float4*)&qkv[(size_t)(b * 1024 + k0 + r) * 3072 + 1024 + h * 64 + c4 * 4];
            int pos = (c4 & 8) | ((c4 & 7) ^ (r & 7));
            uint32_t t[4] = { __float_as_uint(v.x), __float_as_uint(v.y),
                              __float_as_uint(v.z), __float_as_uint(v.w) };
            *(uint4*)&Ks[r * 64 + 4 * pos] = *(uint4*)t;
        }
        // V tile -> Vt [d][key] (transposed)
        for (int i = tid; i < 64 * 16; i += 256) {
            int key = i & 63, dc = i >> 6;
            float4 v = *(const float4*)&qkv[(size_t)(b * 1024 + k0 + key) * 3072 + 2048 + h * 64 + dc * 4];
            int kc = key >> 2, kb = key & 3;
            float e[4] = { v.x, v.y, v.z, v.w };
#pragma unroll
            for (int s = 0; s < 4; ++s) {
                int d = dc * 4 + s;
                int pos = (kc & 8) | ((kc & 7) ^ (d & 7));
                Vt[d * 64 + 4 * pos + kb] = __float_as_uint(e[s]);
            }
        }
        __syncthreads();

        // ---- S = Q @ K^T : warp tile 16x64 ----
        float s[8][4];
#pragma unroll
        for (int j = 0; j < 8; ++j)
#pragma unroll
            for (int r = 0; r < 4; ++r) s[j][r] = 0.f;

#pragma unroll
        for (int kk = 0; kk < 8; ++kk) {
            int ck = kk * 2;
            uint32_t af[4];
            ldsm4(af[0], af[1], af[2], af[3], aswz(Qb, aRowQ, ck + cbitA));
#pragma unroll
            for (int jp = 0; jp < 4; ++jp) {
                uint32_t bf[4];
                ldsm4(bf[0], bf[1], bf[2], bf[3],
                      aswz(Kb, jp * 16 + bRowOff, ck + cbitB));
                mma_tf32(s[2 * jp],     af, &bf[0]);
                mma_tf32(s[2 * jp + 1], af, &bf[2]);
            }
        }

        // ---- mask + online softmax ----
        const int qr0 = q0 + wrp * 16 + g;
        const int qr1 = qr0 + 8;
#pragma unroll
        for (int j = 0; j < 8; ++j) {
            int c0 = k0 + j * 8 + q2 * 2;
            int c1 = c0 + 1;
            if (c0 > qr0 || c0 >= blen) s[j][0] = -1e30f;
            if (c1 > qr0 || c1 >= blen) s[j][1] = -1e30f;
            if (c0 > qr1 || c0 >= blen) s[j][2] = -1e30f;
            if (c1 > qr1 || c1 >= blen) s[j][3] = -1e30f;
        }
        float mx0 = -1e30f, mx1 = -1e30f;
#pragma unroll
        for (int j = 0; j < 8; ++j) {
            mx0 = fmaxf(mx0, fmaxf(s[j][0], s[j][1]));
            mx1 = fmaxf(mx1, fmaxf(s[j][2], s[j][3]));
        }
        mx0 = fmaxf(mx0, __shfl_xor_sync(0xffffffffu, mx0, 1));
        mx0 = fmaxf(mx0, __shfl_xor_sync(0xffffffffu, mx0, 2));
        mx1 = fmaxf(mx1, __shfl_xor_sync(0xffffffffu, mx1, 1));
        mx1 = fmaxf(mx1, __shfl_xor_sync(0xffffffffu, mx1, 2));
        float mn0 = fmaxf(m0r, mx0), mn1 = fmaxf(m1r, mx1);
        float al0 = __expf(m0r - mn0), al1 = __expf(m1r - mn1);
        float sm0 = 0.f, sm1 = 0.f;
#pragma unroll
        for (int j = 0; j < 8; ++j) {
            s[j][0] = __expf(s[j][0] - mn0);
            s[j][1] = __expf(s[j][1] - mn0);
            s[j][2] = __expf(s[j][2] - mn1);
            s[j][3] = __expf(s[j][3] - mn1);
            sm0 += s[j][0] + s[j][1];
            sm1 += s[j][2] + s[j][3];
        }
        sm0 += __shfl_xor_sync(0xffffffffu, sm0, 1);
        sm0 += __shfl_xor_sync(0xffffffffu, sm0, 2);
        sm1 += __shfl_xor_sync(0xffffffffu, sm1, 1);
        sm1 += __shfl_xor_sync(0xffffffffu, sm1, 2);
        l0r = l0r * al0 + sm0;
        l1r = l1r * al1 + sm1;
        m0r = mn0; m1r = mn1;
#pragma unroll
        for (int j = 0; j < 8; ++j) {
            O[j][0] *= al0; O[j][1] *= al0;
            O[j][2] *= al1; O[j][3] *= al1;
        }

        // ---- store P (own warp rows only) ----
#pragma unroll
        for (int j = 0; j < 8; ++j) {
            int key = j * 8 + q2 * 2;
            int kc  = key >> 2;
            int pos = (kc & 8) | ((kc & 7) ^ (g & 7));
            int wrd = (wrp * 16 + g) * 64 + 4 * pos + (key & 3);
            uint32_t p0[2] = { __float_as_uint(s[j][0]), __float_as_uint(s[j][1]) };
            *(uint2*)&Ps[wrd] = *(uint2*)p0;
            uint32_t p1[2] = { __float_as_uint(s[j][2]), __float_as_uint(s[j][3]) };
            *(uint2*)&Ps[wrd + 8 * 64] = *(uint2*)p1;
        }
        __syncwarp();      // P frags are read only by this warp

        // ---- O += P @ V ----
#pragma unroll
        for (int kk = 0; kk < 8; ++kk) {
            int ck = kk * 2;
            uint32_t af[4];
            ldsm4(af[0], af[1], af[2], af[3], aswz(Pb, aRowQ, ck + cbitA));
#pragma unroll
            for (int jp = 0; jp < 4; ++jp) {
                uint32_t bf[4];
                ldsm4(bf[0], bf[1], bf[2], bf[3],
                      aswz(Vb, jp * 16 + bRowOff, ck + cbitB));
                mma_tf32(O[2 * jp],     af, &bf[0]);
                mma_tf32(O[2 * jp + 1], af, &bf[2]);
            }
        }
    }

    // epilogue: normalize, RNA-round to tf32 (feeds the out-proj GEMM exactly)
    const float inv0 = 1.f / l0r, inv1 = 1.f / l1r;
    const int row0 = b * 1024 + q0 + wrp * 16 + g;
#pragma unroll
    for (int j = 0; j < 8; ++j) {
        int d = h * 64 + j * 8 + q2 * 2;
        float2 v0 = { __uint_as_float(f2tf(O[j][0] * inv0)),
                      __uint_as_float(f2tf(O[j][1] * inv0)) };
        float2 v1 = { __uint_as_float(f2tf(O[j][2] * inv1)),
                      __uint_as_float(f2tf(O[j][3] * inv1)) };
        *(float2*)&out[(size_t)row0 * 1024 + d] = v0;
        *(float2*)&out[(size_t)(row0 + 8) * 1024 + d] = v1;
    }
}

// ---------------- LayerNorm ------------------------------------------------
__global__ __launch_bounds__(256) void ln_kernel(
    const float* __restrict__ X, const float* __restrict__ w,
    const float* __restrict__ bb, float* __restrict__ Y)
{
    const int row = blockIdx.x;
    const int t   = threadIdx.x;
    float4 x = *(const float4*)&X[(size_t)row * 1024 + t * 4];
    float s = x.x + x.y + x.z + x.w;
    float q = fmaf(x.x, x.x, fmaf(x.y, x.y, fmaf(x.z, x.z, x.w * x.w)));
#pragma unroll
    for (int off = 16; off; off >>= 1) {
        s += __shfl_xor_sync(0xffffffffu, s, off);
        q += __shfl_xor_sync(0xffffffffu, q, off);
    }
    __shared__ float ss[8], qq[8];
    const int warp = t >> 5, lane = t & 31;
    if (lane == 0) { ss[warp] = s; qq[warp] = q; }
    __syncthreads();
    float S = 0.f, Q2 = 0.f;
#pragma unroll
    for (int i = 0; i < 8; ++i) { S += ss[i]; Q2 += qq[i]; }
    const float mean = S * (1.0f / 1024.0f);
    const float var  = fmaxf(Q2 * (1.0f / 1024.0f) - mean * mean, 0.f);
    const float inv  = rsqrtf(var + 1e-12f);
    float4 wv = *(const float4*)&w[t * 4];
    float4 bv = *(const float4*)&bb[t * 4];
    float4 y;
    y.x = wv.x * (x.x - mean) * inv + bv.x;
    y.y = wv.y * (x.y - mean) * inv + bv.y;
    y.z = wv.z * (x.z - mean) * inv + bv.z;
    y.w = wv.w * (x.w - mean) * inv + bv.w;
    *(float4*)&Y[(size_t)row * 1024 + t * 4] = y;
}

// ---------------- launch ----------------------------------------------------
static constexpr int TG_SMEM = 65536;   // 4 stages x 16KB

extern "C" void kernel_launch(void* const* d_in, const int* in_sizes, int n_in,
                              void* d_out, int out_size)
{
    const float* x     = (const float*)d_in[0];
    const float* in_w  = (const float*)d_in[1];
    const float* in_b  = (const float*)d_in[2];
    const float* out_w = (const float*)d_in[3];
    const float* out_b = (const float*)d_in[4];
    const float* fc1_w = (const float*)d_in[5];
    const float* fc1_b = (const float*)d_in[6];
    const float* fc2_w = (const float*)d_in[7];
    const float* fc2_b = (const float*)d_in[8];
    const float* ln1_w = (const float*)d_in[9];
    const float* ln1_b = (const float*)d_in[10];
    const float* ln2_w = (const float*)d_in[11];
    const float* ln2_b = (const float*)d_in[12];
    const void*  pad   = d_in[13];
    float* out = (float*)d_out;

    float *qkv, *attn, *sbuf, *x1, *ff, *wq;
    int* lenv;
    cudaGetSymbolAddress((void**)&qkv,  g_qkv);
    cudaGetSymbolAddress((void**)&attn, g_attn);
    cudaGetSymbolAddress((void**)&sbuf, g_s);
    cudaGetSymbolAddress((void**)&x1,   g_x1);
    cudaGetSymbolAddress((void**)&ff,   g_ff);
    cudaGetSymbolAddress((void**)&wq,   g_wq);
    cudaGetSymbolAddress((void**)&lenv, g_len);

    float* w_in  = wq;
    float* w_out = wq + 3145728;
    float* w_f1  = wq + 4194304;
    float* w_f2  = wq + 8388608;

    static bool attr_done = false;
    if (!attr_done) {
        cudaFuncSetAttribute(tgemm_kernel<0, false>, cudaFuncAttributeMaxDynamicSharedMemorySize, TG_SMEM);
        cudaFuncSetAttribute(tgemm_kernel<1, false>, cudaFuncAttributeMaxDynamicSharedMemorySize, TG_SMEM);
        cudaFuncSetAttribute(tgemm_kernel<2, true>,  cudaFuncAttributeMaxDynamicSharedMemorySize, TG_SMEM);
        cudaFuncSetAttribute(attn_kernel, cudaFuncAttributeMaxDynamicSharedMemorySize, ATTN_SMEM);
        attr_done = true;
    }

    mask_len_kernel<<<1, 256>>>(pad);
    cvt_all_kernel<<<12288, 256>>>(in_w, out_w, fc1_w, fc2_w, wq);

    // 1) qkv = x @ in_w^T + in_b           [8192, 3072]
    tgemm_kernel<0, false><<<dim3(24, 64), 256, TG_SMEM>>>(x, w_in, in_b, nullptr, qkv, 1024, 3072);
    // 2) attention -> attn (tf32-rounded)  [8192, 1024]; 128-query tiles
    attn_kernel<<<dim3(8, 16, 8), 256, ATTN_SMEM>>>(qkv, lenv, attn);
    // 3) s1 = attn @ out_w^T + out_b + x   [8192, 1024]
    tgemm_kernel<1, false><<<dim3(8, 64), 256, TG_SMEM>>>(attn, w_out, out_b, x, sbuf, 1024, 1024);
    // 4) x1 = LN1(s1)
    ln_kernel<<<8192, 256>>>(sbuf, ln1_w, ln1_b, x1);
    // 5) ff = relu(x1 @ fc1_w^T + fc1_b) (tf32-rounded)  [8192, 4096]
    tgemm_kernel<2, true><<<dim3(32, 64), 256, TG_SMEM>>>(x1, w_f1, fc1_b, nullptr, ff, 1024, 4096);
    // 6) s2 = ff @ fc2_w^T + fc2_b + x1    [8192, 1024]
    tgemm_kernel<1, false><<<dim3(8, 64), 256, TG_SMEM>>>(ff, w_f2, fc2_b, x1, sbuf, 4096, 1024);
    // 7) out = LN2(s2)
    ln_kernel<<<8192, 256>>>(sbuf, ln2_w, ln2_b, out);
}

// round 15
// speedup vs baseline: 1.7110x; 1.7110x over previous
#include <cuda_runtime.h>
#include <cuda_fp16.h>
#include <math.h>
#include <stdint.h>

// Problem dims: B=8, T=1024, E=1024, H=16, HD=64, FF=4096, M = B*T = 8192

// ---------------- scratch (device globals; no allocations allowed) ----------
__device__ __half g_qkv[(size_t)8192 * 3072];
__device__ __half g_attn[(size_t)8192 * 1024];
__device__ float  g_s[(size_t)8192 * 1024];
__device__ float  g_x1[(size_t)8192 * 1024];
__device__ __half g_x1h[(size_t)8192 * 1024];
__device__ __half g_ff[(size_t)8192 * 4096];
__device__ __half g_wh[12582912];   // fp16 weights: in_w 0, out_w 3145728, fc1_w 4194304, fc2_w 8388608
__device__ __half g_xh[(size_t)8192 * 1024];
__device__ int    g_len[8];

// ---------------- padding-mask: dtype detect + parallel length extraction ---
__global__ void mask_len_kernel(const void* mask) {
    __shared__ int flags[3];
    __shared__ int lensh[8];
    const int tid = threadIdx.x;
    if (tid < 3) flags[tid] = 0;
    if (tid < 8) lensh[tid] = 1024;
    __syncthreads();

    const unsigned int* w = (const unsigned int*)mask;
    int f32 = 0, gt1 = 0, eq1 = 0;
    for (int i = tid; i < 2048; i += 256) {
        unsigned int v = w[i];
        if (v == 0x3F800000u)      f32 = 1;
        else if (v == 1u)          eq1 = 1;
        else if (v != 0u)          gt1 = 1;
    }
    if (f32) atomicOr(&flags[0], 1);
    if (gt1) atomicOr(&flags[1], 1);
    if (eq1) atomicOr(&flags[2], 1);
    __syncthreads();

    if (flags[0]) {
        const float* p = (const float*)mask;
        for (int i = tid; i < 8192; i += 256)
            if (p[i] != 0.f) atomicMin(&lensh[i >> 10], i & 1023);
    } else if (flags[1]) {
        const unsigned char* p = (const unsigned char*)mask;
        for (int i = tid; i < 8192; i += 256)
            if (p[i]) atomicMin(&lensh[i >> 10], i & 1023);
    } else if (flags[2]) {
        const int* p = (const int*)mask;
        for (int i = tid; i < 8192; i += 256)
            if (p[i]) atomicMin(&lensh[i >> 10], i & 1023);
    }
    __syncthreads();
    if (tid < 8) g_len[tid] = lensh[tid];
}

// ---------------- common helpers -------------------------------------------
__device__ __forceinline__ void mma_f16(float* d, const uint32_t* a, const uint32_t* b) {
    asm volatile(
        "mma.sync.aligned.m16n8k16.row.col.f32.f16.f16.f32 "
        "{%0,%1,%2,%3}, {%4,%5,%6,%7}, {%8,%9}, {%0,%1,%2,%3};"
        : "+f"(d[0]), "+f"(d[1]), "+f"(d[2]), "+f"(d[3])
        : "r"(a[0]), "r"(a[1]), "r"(a[2]), "r"(a[3]), "r"(b[0]), "r"(b[1]));
}
__device__ __forceinline__ void ldsm4(uint32_t& r0, uint32_t& r1, uint32_t& r2, uint32_t& r3,
                                      uint32_t addr) {
    asm volatile("ldmatrix.sync.aligned.m8n8.x4.shared.b16 {%0,%1,%2,%3}, [%4];"
                 : "=r"(r0), "=r"(r1), "=r"(r2), "=r"(r3) : "r"(addr));
}
__device__ __forceinline__ uint32_t s2u(const void* p) {
    return (uint32_t)__cvta_generic_to_shared(p);
}
__device__ __forceinline__ void cpasync16(uint32_t dst, const void* src) {
    asm volatile("cp.async.cg.shared.global [%0], [%1], 16;"
                 :: "r"(dst), "l"(src) : "memory");
}
__device__ __forceinline__ uint32_t pack_h2(float a, float b) {
    __half2 h = __floats2half2_rn(a, b);
    return *(uint32_t*)&h;
}

// ---------------- merged fp32 -> fp16 conversion (weights + x) --------------
// float4 spans: in_w [0, 786432), out_w [786432, 1048576),
// fc1_w [1048576, 2097152), fc2_w [2097152, 3145728), x [3145728, 5242880).
__global__ __launch_bounds__(256) void cvt_kernel(
    const float* __restrict__ in_w, const float* __restrict__ out_w,
    const float* __restrict__ fc1_w, const float* __restrict__ fc2_w,
    const float* __restrict__ x, __half* __restrict__ wh, __half* __restrict__ xh)
{
    int i = blockIdx.x * 256 + threadIdx.x;     // float4 index, < 5242880
    const float4* src;
    __half* dsth;
    if (i < 786432)       { src = (const float4*)in_w  + i;            dsth = wh + (size_t)i * 4; }
    else if (i < 1048576) { int j = i - 786432;  src = (const float4*)out_w + j; dsth = wh + 3145728 + (size_t)j * 4; }
    else if (i < 2097152) { int j = i - 1048576; src = (const float4*)fc1_w + j; dsth = wh + 4194304 + (size_t)j * 4; }
    else if (i < 3145728) { int j = i - 2097152; src = (const float4*)fc2_w + j; dsth = wh + 8388608 + (size_t)j * 4; }
    else                  { int j = i - 3145728; src = (const float4*)x + j;     dsth = xh + (size_t)j * 4; }
    float4 v = *src;
    uint2 o = { pack_h2(v.x, v.y), pack_h2(v.z, v.w) };
    *(uint2*)dsth = o;
}

// ---------------- fp16 tensor-core GEMM -------------------------------------
// C[M,N] = A[M,K] @ W[N,K]^T + bias (+res/+relu), fp32 accumulate.
// 128x128 tile, kstep 32 halfs (64B rows), 8 warps (4m x 2n), warp 32x64.
// SMEM: 4 stages x 16KB; swizzle: 16B chunk c of row r at byte
// r*64 + 16*(c ^ ((r>>1)&3)).  One barrier per k-tile, wait_group 2,
// prefetch kt+3; k16 step 1 = address XOR 32.
template <int EPI, bool OUT_HALF>  // EPI 0: +bias, 1: +bias+res, 2: +bias+relu
__global__ __launch_bounds__(256, 2) void hgemm_kernel(
    const __half* __restrict__ A, const __half* __restrict__ W,
    const float* __restrict__ bias, const float* __restrict__ R,
    void* __restrict__ Cv, int Ksz, int Nsz)
{
    extern __shared__ uint32_t smem[];   // 4 stages x 16KB = 64KB
    const uint32_t sbase = s2u(smem);

    const int tid  = threadIdx.x;
    const int lane = tid & 31;
    const int warp = tid >> 5;
    const int wm   = warp & 3;
    const int wn   = warp >> 2;
    const int m0   = blockIdx.y * 128;
    const int n0   = blockIdx.x * 128;

    const __half* srcp[4];
    uint32_t      dsto[4];
#pragma unroll
    for (int i = 0; i < 4; ++i) {
        int idx = i * 256 + tid;
        if (idx < 512) {
            int row = idx >> 2, c = idx & 3;
            srcp[i] = A + (size_t)(m0 + row) * Ksz + c * 8;
            dsto[i] = row * 64 + 16 * (c ^ ((row >> 1) & 3));
        } else {
            int j = idx - 512;
            int row = j >> 2, c = j & 3;
            srcp[i] = W + (size_t)(n0 + row) * Ksz + c * 8;
            dsto[i] = 8192 + row * 64 + 16 * (c ^ ((row >> 1) & 3));
        }
    }

    const int mat = lane >> 3, rr = lane & 7;
    const int ar  = wm * 32 + (mat & 1) * 8 + rr;
    const int cbA = mat >> 1;
    const uint32_t aA = sbase + ar * 64 + 16 * (cbA ^ ((ar >> 1) & 3));
    const int br  = wn * 64 + (mat >> 1) * 8 + rr;
    const int cbB = mat & 1;
    const uint32_t aB = sbase + 8192 + br * 64 + 16 * (cbB ^ ((br >> 1) & 3));

    float acc[2][8][4];
#pragma unroll
    for (int i = 0; i < 2; ++i)
#pragma unroll
        for (int j = 0; j < 8; ++j)
#pragma unroll
            for (int r = 0; r < 4; ++r) acc[i][j][r] = 0.f;

    const int KT = Ksz >> 5;             // k-tiles of 32 halfs

#pragma unroll
    for (int p = 0; p < 3; ++p) {
        const uint32_t st = sbase + p * 16384;
#pragma unroll
        for (int i = 0; i < 4; ++i)
            cpasync16(st + dsto[i], srcp[i] + p * 32);
        asm volatile("cp.async.commit_group;" ::: "memory");
    }

    for (int kt = 0; kt < KT; ++kt) {
        asm volatile("cp.async.wait_group 2;" ::: "memory");
        __syncthreads();

        if (kt + 3 < KT) {
            const uint32_t st = sbase + ((kt + 3) & 3) * 16384;
#pragma unroll
            for (int i = 0; i < 4; ++i)
                cpasync16(st + dsto[i], srcp[i] + (kt + 3) * 32);
        }
        asm volatile("cp.async.commit_group;" ::: "memory");

        const uint32_t off = (kt & 3) * 16384;
        const uint32_t aAb = aA + off;
        const uint32_t aBb = aB + off;
#pragma unroll
        for (int k16 = 0; k16 < 2; ++k16) {
            const uint32_t xo = k16 << 5;
            uint32_t af0[4], af1[4];
            ldsm4(af0[0], af0[1], af0[2], af0[3], aAb ^ xo);
            ldsm4(af1[0], af1[1], af1[2], af1[3], (aAb + 1024) ^ xo);
#pragma unroll
            for (int jp = 0; jp < 4; ++jp) {
                uint32_t bf[4];
                ldsm4(bf[0], bf[1], bf[2], bf[3], (aBb + jp * 1024) ^ xo);
                mma_f16(acc[0][2 * jp],     af0, &bf[0]);
                mma_f16(acc[1][2 * jp],     af1, &bf[0]);
                mma_f16(acc[0][2 * jp + 1], af0, &bf[2]);
                mma_f16(acc[1][2 * jp + 1], af1, &bf[2]);
            }
        }
    }

    float*  Cf = (float*)Cv;
    __half* Ch = (__half*)Cv;
#pragma unroll
    for (int i = 0; i < 2; ++i) {
        int row = m0 + wm * 32 + i * 16 + (lane >> 2);
#pragma unroll
        for (int j = 0; j < 8; ++j) {
            int col = n0 + wn * 64 + j * 8 + (lane & 3) * 2;
            float b0v = bias[col], b1v = bias[col + 1];
            size_t o0 = (size_t)row * Nsz + col;
            size_t o1 = (size_t)(row + 8) * Nsz + col;
            float v0 = acc[i][j][0] + b0v, v1 = acc[i][j][1] + b1v;
            float v2 = acc[i][j][2] + b0v, v3 = acc[i][j][3] + b1v;
            if (EPI == 1) {
                v0 += R[o0]; v1 += R[o0 + 1];
                v2 += R[o1]; v3 += R[o1 + 1];
            }
            if (EPI == 2) {
                v0 = fmaxf(v0, 0.f); v1 = fmaxf(v1, 0.f);
                v2 = fmaxf(v2, 0.f); v3 = fmaxf(v3, 0.f);
            }
            if (OUT_HALF) {
                *(uint32_t*)&Ch[o0] = pack_h2(v0, v1);
                *(uint32_t*)&Ch[o1] = pack_h2(v2, v3);
            } else {
                float2 q0v = { v0, v1 }, q1v = { v2, v3 };
                *(float2*)&Cf[o0] = q0v;
                *(float2*)&Cf[o1] = q1v;
            }
        }
    }
}

// ---------------- attention: fp16 mma flash, per (b, h, 64-query tile) ------
// Tiles 64x64 halfs = 128B rows (8 chunks), swizzle: chunk c of row r at
// byte r*128 + 16*(c ^ (r&7)).  Q/K/Vt/P each 8KB (static 32KB).
__device__ __forceinline__ uint32_t aswz(uint32_t base, int row, int chunk) {
    return base + row * 128 + 16 * (chunk ^ (row & 7));
}

__global__ __launch_bounds__(128) void attn_kernel(
    const __half* __restrict__ qkv, const int* __restrict__ lenv,
    __half* __restrict__ out)
{
    __shared__ uint32_t Qs[2048];   // 64 x 128B
    __shared__ uint32_t Ks[2048];
    __shared__ uint32_t Vt[2048];   // transposed [d][key]
    __shared__ uint32_t Ps[2048];

    const int tid  = threadIdx.x;
    const int lane = tid & 31;
    const int wrp  = tid >> 5;
    const int b    = blockIdx.z;
    const int h    = blockIdx.y;
    const int qt   = blockIdx.x;
    const int q0   = qt * 64;
    const int blen = lenv[b];

    const uint32_t Qb = s2u(Qs), Kb = s2u(Ks), Vb = s2u(Vt), Pb = s2u(Ps);

    {
        __half2 hs = __float2half2_rn(0.125f);
        for (int i = tid; i < 512; i += 128) {
            int r = i >> 3, c = i & 7;
            uint4 v = *(const uint4*)(qkv + (size_t)(b * 1024 + q0 + r) * 3072 + h * 64 + c * 8);
            __half2* hv = (__half2*)&v;
            hv[0] = __hmul2(hv[0], hs); hv[1] = __hmul2(hv[1], hs);
            hv[2] = __hmul2(hv[2], hs); hv[3] = __hmul2(hv[3], hs);
            *(uint4*)((char*)Qs + r * 128 + 16 * (c ^ (r & 7))) = v;
        }
    }

    const int mat = lane >> 3, rr = lane & 7;
    const int g   = lane >> 2;
    const int q2  = lane & 3;
    const int aRowQ = wrp * 16 + (mat & 1) * 8 + rr;
    const int cbitA = mat >> 1;
    const int cbitB = mat & 1;
    const int bRowOff = (mat >> 1) * 8 + rr;

    const uint32_t aQ = aswz(Qb, aRowQ, cbitA);
    const uint32_t aP = aswz(Pb, aRowQ, cbitA);

    float O[8][4];
    float m0r = -1e30f, m1r = -1e30f, l0r = 0.f, l1r = 0.f;
#pragma unroll
    for (int j = 0; j < 8; ++j)
#pragma unroll
        for (int r = 0; r < 4; ++r) O[j][r] = 0.f;

    for (int kt = 0; kt <= qt && kt * 64 < blen; ++kt) {
        const int k0 = kt * 64;
        __syncthreads();

        for (int i = tid; i < 512; i += 128) {
            int r = i >> 3, c = i & 7;
            uint4 v = *(const uint4*)(qkv + (size_t)(b * 1024 + k0 + r) * 3072 + 1024 + h * 64 + c * 8);
            *(uint4*)((char*)Ks + r * 128 + 16 * (c ^ (r & 7))) = v;
        }
        for (int i = tid; i < 512; i += 128) {
            int key = i >> 3, hc = i & 7;
            uint4 v = *(const uint4*)(qkv + (size_t)(b * 1024 + k0 + key) * 3072 + 2048 + h * 64 + hc * 8);
            const __half* hp = (const __half*)&v;
            int kchunk = key >> 3, kin = (key & 7) * 2;
#pragma unroll
            for (int s = 0; s < 8; ++s) {
                int d = hc * 8 + s;
                *(__half*)((char*)Vt + d * 128 + 16 * (kchunk ^ (d & 7)) + kin) = hp[s];
            }
        }
        __syncthreads();

        float s[8][4];
#pragma unroll
        for (int j = 0; j < 8; ++j)
#pragma unroll
            for (int r = 0; r < 4; ++r) s[j][r] = 0.f;

#pragma unroll
        for (int kk = 0; kk < 4; ++kk) {
            const uint32_t xo = kk << 5;
            uint32_t af[4];
            ldsm4(af[0], af[1], af[2], af[3], aQ ^ xo);
#pragma unroll
            for (int jp = 0; jp < 4; ++jp) {
                uint32_t bf[4];
                ldsm4(bf[0], bf[1], bf[2], bf[3],
                      aswz(Kb, jp * 16 + bRowOff, cbitB) ^ xo);
                mma_f16(s[2 * jp],     af, &bf[0]);
                mma_f16(s[2 * jp + 1], af, &bf[2]);
            }
        }

        const int qr0 = q0 + wrp * 16 + g;
        const int qr1 = qr0 + 8;
#pragma unroll
        for (int j = 0; j < 8; ++j) {
            int c0 = k0 + j * 8 + q2 * 2;
            int c1 = c0 + 1;
            if (c0 > qr0 || c0 >= blen) s[j][0] = -1e30f;
            if (c1 > qr0 || c1 >= blen) s[j][1] = -1e30f;
            if (c0 > qr1 || c0 >= blen) s[j][2] = -1e30f;
            if (c1 > qr1 || c1 >= blen) s[j][3] = -1e30f;
        }
        float mx0 = -1e30f, mx1 = -1e30f;
#pragma unroll
        for (int j = 0; j < 8; ++j) {
            mx0 = fmaxf(mx0, fmaxf(s[j][0], s[j][1]));
            mx1 = fmaxf(mx1, fmaxf(s[j][2], s[j][3]));
        }
        mx0 = fmaxf(mx0, __shfl_xor_sync(0xffffffffu, mx0, 1));
        mx0 = fmaxf(mx0, __shfl_xor_sync(0xffffffffu, mx0, 2));
        mx1 = fmaxf(mx1, __shfl_xor_sync(0xffffffffu, mx1, 1));
        mx1 = fmaxf(mx1, __shfl_xor_sync(0xffffffffu, mx1, 2));
        float mn0 = fmaxf(m0r, mx0), mn1 = fmaxf(m1r, mx1);
        float al0 = __expf(m0r - mn0), al1 = __expf(m1r - mn1);
        float sm0 = 0.f, sm1 = 0.f;
#pragma unroll
        for (int j = 0; j < 8; ++j) {
            s[j][0] = __expf(s[j][0] - mn0);
            s[j][1] = __expf(s[j][1] - mn0);
            s[j][2] = __expf(s[j][2] - mn1);
            s[j][3] = __expf(s[j][3] - mn1);
            sm0 += s[j][0] + s[j][1];
            sm1 += s[j][2] + s[j][3];
        }
        sm0 += __shfl_xor_sync(0xffffffffu, sm0, 1);
        sm0 += __shfl_xor_sync(0xffffffffu, sm0, 2);
        sm1 += __shfl_xor_sync(0xffffffffu, sm1, 1);
        sm1 += __shfl_xor_sync(0xffffffffu, sm1, 2);
        l0r = l0r * al0 + sm0;
        l1r = l1r * al1 + sm1;
        m0r = mn0; m1r = mn1;
#pragma unroll
        for (int j = 0; j < 8; ++j) {
            O[j][0] *= al0; O[j][1] *= al0;
            O[j][2] *= al1; O[j][3] *= al1;
        }

        {
            int row0 = wrp * 16 + g;
            int row1 = row0 + 8;
#pragma unroll
            for (int j = 0; j < 8; ++j) {
                int off0 = row0 * 128 + 16 * (j ^ (row0 & 7)) + q2 * 4;
                int off1 = row1 * 128 + 16 * (j ^ (row1 & 7)) + q2 * 4;
                *(uint32_t*)((char*)Ps + off0) = pack_h2(s[j][0], s[j][1]);
                *(uint32_t*)((char*)Ps + off1) = pack_h2(s[j][2], s[j][3]);
            }
        }
        __syncwarp();

#pragma unroll
        for (int kk = 0; kk < 4; ++kk) {
            const uint32_t xo = kk << 5;
            uint32_t af[4];
            ldsm4(af[0], af[1], af[2], af[3], aP ^ xo);
#pragma unroll
            for (int jp = 0; jp < 4; ++jp) {
                uint32_t bf[4];
                ldsm4(bf[0], bf[1], bf[2], bf[3],
                      aswz(Vb, jp * 16 + bRowOff, cbitB) ^ xo);
                mma_f16(O[2 * jp],     af, &bf[0]);
                mma_f16(O[2 * jp + 1], af, &bf[2]);
            }
        }
    }

    const float inv0 = 1.f / l0r, inv1 = 1.f / l1r;
    const int row0 = b * 1024 + q0 + wrp * 16 + g;
#pragma unroll
    for (int j = 0; j < 8; ++j) {
        int d = h * 64 + j * 8 + q2 * 2;
        *(uint32_t*)&out[(size_t)row0 * 1024 + d] = pack_h2(O[j][0] * inv0, O[j][1] * inv0);
        *(uint32_t*)&out[(size_t)(row0 + 8) * 1024 + d] = pack_h2(O[j][2] * inv1, O[j][3] * inv1);
    }
}

// ---------------- LayerNorm (fp32 out + optional fp16 copy) -----------------
__global__ __launch_bounds__(256) void ln_kernel(
    const float* __restrict__ X, const float* __restrict__ w,
    const float* __restrict__ bb, float* __restrict__ Y,
    __half* __restrict__ Yh)
{
    const int row = blockIdx.x;
    const int t   = threadIdx.x;
    float4 x = *(const float4*)&X[(size_t)row * 1024 + t * 4];
    float s = x.x + x.y + x.z + x.w;
    float q = fmaf(x.x, x.x, fmaf(x.y, x.y, fmaf(x.z, x.z, x.w * x.w)));
#pragma unroll
    for (int off = 16; off; off >>= 1) {
        s += __shfl_xor_sync(0xffffffffu, s, off);
        q += __shfl_xor_sync(0xffffffffu, q, off);
    }
    __shared__ float ss[8], qq[8];
    const int warp = t >> 5, lane = t & 31;
    if (lane == 0) { ss[warp] = s; qq[warp] = q; }
    __syncthreads();
    float S = 0.f, Q2 = 0.f;
#pragma unroll
    for (int i = 0; i < 8; ++i) { S += ss[i]; Q2 += qq[i]; }
    const float mean = S * (1.0f / 1024.0f);
    const float var  = fmaxf(Q2 * (1.0f / 1024.0f) - mean * mean, 0.f);
    const float inv  = rsqrtf(var + 1e-12f);
    float4 wv = *(const float4*)&w[t * 4];
    float4 bv = *(const float4*)&bb[t * 4];
    float4 y;
    y.x = wv.x * (x.x - mean) * inv + bv.x;
    y.y = wv.y * (x.y - mean) * inv + bv.y;
    y.z = wv.z * (x.z - mean) * inv + bv.z;
    y.w = wv.w * (x.w - mean) * inv + bv.w;
    *(float4*)&Y[(size_t)row * 1024 + t * 4] = y;
    if (Yh) {
        uint2 o = { pack_h2(y.x, y.y), pack_h2(y.z, y.w) };
        *(uint2*)&Yh[(size_t)row * 1024 + t * 4] = o;
    }
}

// ---------------- launch ----------------------------------------------------
static constexpr int TG_SMEM = 65536;   // 4 stages x 16KB

extern "C" void kernel_launch(void* const* d_in, const int* in_sizes, int n_in,
                              void* d_out, int out_size)
{
    const float* x     = (const float*)d_in[0];
    const float* in_w  = (const float*)d_in[1];
    const float* in_b  = (const float*)d_in[2];
    const float* out_w = (const float*)d_in[3];
    const float* out_b = (const float*)d_in[4];
    const float* fc1_w = (const float*)d_in[5];
    const float* fc1_b = (const float*)d_in[6];
    const float* fc2_w = (const float*)d_in[7];
    const float* fc2_b = (const float*)d_in[8];
    const float* ln1_w = (const float*)d_in[9];
    const float* ln1_b = (const float*)d_in[10];
    const float* ln2_w = (const float*)d_in[11];
    const float* ln2_b = (const float*)d_in[12];
    const void*  pad   = d_in[13];
    float* out = (float*)d_out;

    __half *qkv, *attn, *x1h, *ff, *wh, *xh;
    float *sbuf, *x1;
    int* lenv;
    cudaGetSymbolAddress((void**)&qkv,  g_qkv);
    cudaGetSymbolAddress((void**)&attn, g_attn);
    cudaGetSymbolAddress((void**)&sbuf, g_s);
    cudaGetSymbolAddress((void**)&x1,   g_x1);
    cudaGetSymbolAddress((void**)&x1h,  g_x1h);
    cudaGetSymbolAddress((void**)&ff,   g_ff);
    cudaGetSymbolAddress((void**)&wh,   g_wh);
    cudaGetSymbolAddress((void**)&xh,   g_xh);
    cudaGetSymbolAddress((void**)&lenv, g_len);

    __half* w_in  = wh;
    __half* w_out = wh + 3145728;
    __half* w_f1  = wh + 4194304;
    __half* w_f2  = wh + 8388608;

    static bool attr_done = false;
    if (!attr_done) {
        cudaFuncSetAttribute(hgemm_kernel<0, true>,  cudaFuncAttributeMaxDynamicSharedMemorySize, TG_SMEM);
        cudaFuncSetAttribute(hgemm_kernel<1, false>, cudaFuncAttributeMaxDynamicSharedMemorySize, TG_SMEM);
        cudaFuncSetAttribute(hgemm_kernel<2, true>,  cudaFuncAttributeMaxDynamicSharedMemorySize, TG_SMEM);
        attr_done = true;
    }

    mask_len_kernel<<<1, 256>>>(pad);
    // fp32 -> fp16: weights (3,145,728 float4) + x (2,097,152 float4) = 5,242,880
    cvt_kernel<<<20480, 256>>>(in_w, out_w, fc1_w, fc2_w, x, wh, xh);

    // 1) qkv = xh @ in_w^T + in_b          [8192, 3072] fp16 out
    hgemm_kernel<0, true><<<dim3(24, 64), 256, TG_SMEM>>>(xh, w_in, in_b, nullptr, qkv, 1024, 3072);
    // 2) attention -> attn (fp16)          [8192, 1024]
    attn_kernel<<<dim3(16, 16, 8), 128>>>(qkv, lenv, attn);
    // 3) s1 = attn @ out_w^T + out_b + x   [8192, 1024] fp32 out
    hgemm_kernel<1, false><<<dim3(8, 64), 256, TG_SMEM>>>(attn, w_out, out_b, x, sbuf, 1024, 1024);
    // 4) x1 = LN1(s1) (fp32 + fp16 copy)
    ln_kernel<<<8192, 256>>>(sbuf, ln1_w, ln1_b, x1, x1h);
    // 5) ff = relu(x1h @ fc1_w^T + fc1_b)  [8192, 4096] fp16 out
    hgemm_kernel<2, true><<<dim3(32, 64), 256, TG_SMEM>>>(x1h, w_f1, fc1_b, nullptr, ff, 1024, 4096);
    // 6) s2 = ff @ fc2_w^T + fc2_b + x1    [8192, 1024] fp32 out
    hgemm_kernel<1, false><<<dim3(8, 64), 256, TG_SMEM>>>(ff, w_f2, fc2_b, x1, sbuf, 4096, 1024);
    // 7) out = LN2(s2)
    ln_kernel<<<8192, 256>>>(sbuf, ln2_w, ln2_b, out, nullptr);
}